// round 8
// baseline (speedup 1.0000x reference)
#include <cuda_runtime.h>
#include <cstdint>

#define NROWS 16384   // B*M*P = 8*4*512
#define HID   768
#define NH    12
#define HS    64
#define PSEQ  512

// Scratch (allocation-free rule: __device__ globals)
__device__ float g_xtf[NROWS * HID];
__device__ float g_wtf[4 * HID * HID];
__device__ float g_q[NROWS * HID];
__device__ float g_k[NROWS * HID];
__device__ float g_v[NROWS * HID];
__device__ float g_ctx[NROWS * HID];

// ---------------------------------------------------------------------------
// helpers
// ---------------------------------------------------------------------------
__device__ __forceinline__ uint32_t f2tf32(float f) {
    uint32_t r;
    asm("cvt.rna.tf32.f32 %0, %1;" : "=r"(r) : "f"(f));
    return r;
}
__device__ __forceinline__ uint32_t smem_u32(const void* p) {
    uint32_t a;
    asm("{ .reg .u64 t; cvta.to.shared.u64 t, %1; cvt.u32.u64 %0, t; }" : "=r"(a) : "l"(p));
    return a;
}
#define CP16(dst_u32, src_ptr) \
    asm volatile("cp.async.cg.shared.global [%0], [%1], 16;" :: "r"(dst_u32), "l"(src_ptr) : "memory")
#define CP_COMMIT() asm volatile("cp.async.commit_group;" ::: "memory")
#define CP_WAIT(n)  asm volatile("cp.async.wait_group %0;" :: "n"(n) : "memory")

// D += A*B, m16n8k8 tf32 (row.col)
#define MMA_TF32(d, a, b0, b1) \
    asm volatile("mma.sync.aligned.m16n8k8.row.col.f32.tf32.tf32.f32 " \
        "{%0,%1,%2,%3}, {%4,%5,%6,%7}, {%8,%9}, {%0,%1,%2,%3};" \
        : "+f"((d)[0]), "+f"((d)[1]), "+f"((d)[2]), "+f"((d)[3]) \
        : "r"((a)[0]), "r"((a)[1]), "r"((a)[2]), "r"((a)[3]), "r"(b0), "r"(b1))

// ---------------------------------------------------------------------------
// Pre-round fp32 -> tf32-in-fp32.
// ---------------------------------------------------------------------------
__global__ __launch_bounds__(256) void round_tf32_k(
    const float* __restrict__ in, float* __restrict__ out, int n4)
{
    int i = blockIdx.x * 256 + threadIdx.x;
    if (i < n4) {
        float4 v = ((const float4*)in)[i];
        ((uint4*)out)[i] = make_uint4(f2tf32(v.x), f2tf32(v.y), f2tf32(v.z), f2tf32(v.w));
    }
}
// batched: 4 weight matrices in one launch (blockIdx.y selects source)
__global__ __launch_bounds__(256) void round_w4_k(
    const float* __restrict__ w0, const float* __restrict__ w1,
    const float* __restrict__ w2, const float* __restrict__ w3,
    float* __restrict__ out, int n4each)
{
    const float* src = (blockIdx.y == 0) ? w0 : (blockIdx.y == 1) ? w1
                     : (blockIdx.y == 2) ? w2 : w3;
    float* dst = out + (size_t)blockIdx.y * n4each * 4;
    int i = blockIdx.x * 256 + threadIdx.x;
    if (i < n4each) {
        float4 v = ((const float4*)src)[i];
        ((uint4*)dst)[i] = make_uint4(f2tf32(v.x), f2tf32(v.y), f2tf32(v.z), f2tf32(v.w));
    }
}

// ===========================================================================
// GEMM: C[16384,768] = A @ W + bias  (A, W pre-rounded to tf32)
// tile 128x128x32, 128 threads = 4 warps (2x2), warp tile 64x64.
// 2-stage cp.async pipeline; BS_STRIDE=136 (=8 mod 32) -> conflict-free B frags.
// ===========================================================================
#define AS_STRIDE 36    // dwords; =4 mod 32 -> A-frag lanes gid*4+tig distinct
#define BS_STRIDE 136   // dwords; =8 mod 32 -> B-frag lanes tig*8+gid distinct
#define A_BUF (128 * AS_STRIDE)
#define B_BUF (32 * BS_STRIDE)
#define KITERS (HID / 32)   // 24
#define GEMM_SMEM ((2 * A_BUF + 2 * B_BUF) * 4)   // 71680 bytes

__global__ __launch_bounds__(128) void gemm_mma(
    const float* __restrict__ A, const float* __restrict__ W,
    const float* __restrict__ bias, float* __restrict__ C, int round_out)
{
    extern __shared__ __align__(16) uint32_t sm[];
    uint32_t* AsBase = sm;                 // [2][A_BUF]
    uint32_t* BsBase = sm + 2 * A_BUF;     // [2][B_BUF]
    const uint32_t as_addr = smem_u32(AsBase);
    const uint32_t bs_addr = smem_u32(BsBase);

    const int tid = threadIdx.x;
    const int wid = tid >> 5;
    const int lane = tid & 31;
    const int gid = lane >> 2;
    const int tig = lane & 3;
    const int wm = wid >> 1;       // 0..1 -> 64 rows
    const int wn = wid & 1;        // 0..1 -> 64 cols
    const int bm = blockIdx.y * 128;
    const int bn = blockIdx.x * 128;

    float acc[4][8][4] = {};

    auto issue_tile = [&](int it) {
        const int k0 = it * 32;
        const uint32_t ad = as_addr + (uint32_t)((it & 1) * A_BUF * 4);
        const uint32_t bd = bs_addr + (uint32_t)((it & 1) * B_BUF * 4);
#pragma unroll
        for (int u = 0; u < 8; u++) {
            int idx = u * 128 + tid;
            int r = idx >> 3, c4 = idx & 7;
            CP16(ad + (uint32_t)(r * AS_STRIDE + c4 * 4) * 4,
                 A + (size_t)(bm + r) * HID + k0 + c4 * 4);
        }
#pragma unroll
        for (int u = 0; u < 8; u++) {
            int idx = u * 128 + tid;
            int kr = idx >> 5, nc = idx & 31;
            CP16(bd + (uint32_t)(kr * BS_STRIDE + nc * 4) * 4,
                 W + (size_t)(k0 + kr) * HID + bn + nc * 4);
        }
    };

    issue_tile(0);
    CP_COMMIT();

#pragma unroll 1
    for (int it = 0; it < KITERS; it++) {
        if (it + 1 < KITERS) {
            issue_tile(it + 1);
            CP_COMMIT();
            CP_WAIT(1);
        } else {
            CP_WAIT(0);
        }
        __syncthreads();

        const uint32_t* As = AsBase + (it & 1) * A_BUF;
        const uint32_t* Bs = BsBase + (it & 1) * B_BUF;
#pragma unroll
        for (int ks = 0; ks < 4; ks++) {
            uint32_t a[4][4];
#pragma unroll
            for (int mt = 0; mt < 4; mt++) {
                const uint32_t* p = &As[(wm * 64 + mt * 16 + gid) * AS_STRIDE + ks * 8 + tig];
                a[mt][0] = p[0];
                a[mt][1] = p[8 * AS_STRIDE];
                a[mt][2] = p[4];
                a[mt][3] = p[8 * AS_STRIDE + 4];
            }
#pragma unroll
            for (int nt = 0; nt < 8; nt++) {
                const uint32_t* p = &Bs[(ks * 8 + tig) * BS_STRIDE + wn * 64 + nt * 8 + gid];
                uint32_t b0 = p[0];
                uint32_t b1 = p[4 * BS_STRIDE];
#pragma unroll
                for (int mt = 0; mt < 4; mt++)
                    MMA_TF32(acc[mt][nt], a[mt], b0, b1);
            }
        }
        __syncthreads();
    }

    // epilogue
#pragma unroll
    for (int nt = 0; nt < 8; nt++) {
        int c = bn + wn * 64 + nt * 8 + tig * 2;
        float b0 = bias[c], b1 = bias[c + 1];
#pragma unroll
        for (int mt = 0; mt < 4; mt++) {
            int r0 = bm + wm * 64 + mt * 16 + gid;
            float o00 = acc[mt][nt][0] + b0, o01 = acc[mt][nt][1] + b1;
            float o10 = acc[mt][nt][2] + b0, o11 = acc[mt][nt][3] + b1;
            if (round_out) {
                o00 = __uint_as_float(f2tf32(o00));
                o01 = __uint_as_float(f2tf32(o01));
                o10 = __uint_as_float(f2tf32(o10));
                o11 = __uint_as_float(f2tf32(o11));
            }
            *(float2*)(C + (size_t)r0 * HID + c) = make_float2(o00, o01);
            *(float2*)(C + (size_t)(r0 + 8) * HID + c) = make_float2(o10, o11);
        }
    }
}

// ===========================================================================
// Flash attention, mma.sync tf32.
// 128 thr / 4 warps; q-tile 64 (16 rows/warp); KV tiles 64.
// P stays in registers: C-frag -> A-frag via shfl.idx permute (no smem trip).
// K buffer stride 68 (=4 mod 32), V buffer stride 72 (=8 mod 32): both
// fragment-read patterns conflict-free.
// ===========================================================================
#define FS_K 68
#define FS_V 72

__global__ __launch_bounds__(128) void flash_mma(
    const float* __restrict__ Q, const float* __restrict__ K,
    const float* __restrict__ V, float* __restrict__ O)
{
    __shared__ __align__(16) uint32_t Ks[64 * FS_K];
    __shared__ __align__(16) uint32_t Vs[64 * FS_V];
    const uint32_t kb = smem_u32(Ks);
    const uint32_t vb = smem_u32(Vs);

    const int tid = threadIdx.x;
    const int wid = tid >> 5;
    const int lane = tid & 31;
    const int gid = lane >> 2;
    const int tig = lane & 3;
    const int q0 = blockIdx.x * 64;
    const int head = blockIdx.y;
    const int bmi = blockIdx.z;
    const size_t rowbase = (size_t)bmi * PSEQ;
    const int colbase = head * HS;

    // ---- load Q tile (64x64) into Ks, lift to register fragments
#pragma unroll
    for (int u = 0; u < 8; u++) {
        int idx = u * 128 + tid;
        int r = idx >> 4, c4 = idx & 15;
        CP16(kb + (uint32_t)(r * FS_K + c4 * 4) * 4,
             Q + (rowbase + q0 + r) * HID + colbase + c4 * 4);
    }
    CP_COMMIT();
    CP_WAIT(0);
    __syncthreads();
    uint32_t qf[8][4];
#pragma unroll
    for (int ks = 0; ks < 8; ks++) {
        const uint32_t* p = &Ks[(wid * 16 + gid) * FS_K + ks * 8 + tig];
        qf[ks][0] = p[0];
        qf[ks][1] = p[8 * FS_K];
        qf[ks][2] = p[4];
        qf[ks][3] = p[8 * FS_K + 4];
    }
    __syncthreads();

    // first K/V tile
#pragma unroll
    for (int u = 0; u < 8; u++) {
        int idx = u * 128 + tid;
        int r = idx >> 4, c4 = idx & 15;
        CP16(kb + (uint32_t)(r * FS_K + c4 * 4) * 4,
             K + (rowbase + r) * HID + colbase + c4 * 4);
        CP16(vb + (uint32_t)(r * FS_V + c4 * 4) * 4,
             V + (rowbase + r) * HID + colbase + c4 * 4);
    }
    CP_COMMIT();

    float m0 = -1e30f, m1 = -1e30f, l0 = 0.f, l1 = 0.f;
    float oacc[8][4] = {};

    const int srcA = (lane & 28) | (tig >> 1);   // gid*4 + tig/2
    const int srcB = srcA + 2;
    const bool odd = tig & 1;

#pragma unroll 1
    for (int n0 = 0; n0 < PSEQ; n0 += 64) {
        CP_WAIT(0);
        __syncthreads();

        // ---- S = Q K^T (warp's 16 q-rows x 64 kv)
        float sacc[8][4] = {};
#pragma unroll
        for (int ks = 0; ks < 8; ks++) {
#pragma unroll
            for (int nt = 0; nt < 8; nt++) {
                const uint32_t* p = &Ks[(nt * 8 + gid) * FS_K + ks * 8 + tig];
                MMA_TF32(sacc[nt], qf[ks], p[0], p[4]);
            }
        }

        // ---- online softmax in registers
        float rmax0 = -1e30f, rmax1 = -1e30f;
#pragma unroll
        for (int nt = 0; nt < 8; nt++) {
            sacc[nt][0] *= 0.125f; sacc[nt][1] *= 0.125f;
            sacc[nt][2] *= 0.125f; sacc[nt][3] *= 0.125f;
            rmax0 = fmaxf(rmax0, fmaxf(sacc[nt][0], sacc[nt][1]));
            rmax1 = fmaxf(rmax1, fmaxf(sacc[nt][2], sacc[nt][3]));
        }
        rmax0 = fmaxf(rmax0, __shfl_xor_sync(0xffffffffu, rmax0, 1));
        rmax0 = fmaxf(rmax0, __shfl_xor_sync(0xffffffffu, rmax0, 2));
        rmax1 = fmaxf(rmax1, __shfl_xor_sync(0xffffffffu, rmax1, 1));
        rmax1 = fmaxf(rmax1, __shfl_xor_sync(0xffffffffu, rmax1, 2));
        float m0n = fmaxf(m0, rmax0);
        float m1n = fmaxf(m1, rmax1);
        float alpha0 = __expf(m0 - m0n);
        float alpha1 = __expf(m1 - m1n);
        float rs0 = 0.f, rs1 = 0.f;
#pragma unroll
        for (int nt = 0; nt < 8; nt++) {
            sacc[nt][0] = __expf(sacc[nt][0] - m0n);
            sacc[nt][1] = __expf(sacc[nt][1] - m0n);
            sacc[nt][2] = __expf(sacc[nt][2] - m1n);
            sacc[nt][3] = __expf(sacc[nt][3] - m1n);
            rs0 += sacc[nt][0] + sacc[nt][1];
            rs1 += sacc[nt][2] + sacc[nt][3];
        }
        rs0 += __shfl_xor_sync(0xffffffffu, rs0, 1);
        rs0 += __shfl_xor_sync(0xffffffffu, rs0, 2);
        rs1 += __shfl_xor_sync(0xffffffffu, rs1, 1);
        rs1 += __shfl_xor_sync(0xffffffffu, rs1, 2);
        l0 = l0 * alpha0 + rs0;
        l1 = l1 * alpha1 + rs1;
        m0 = m0n; m1 = m1n;
#pragma unroll
        for (int dt = 0; dt < 8; dt++) {
            oacc[dt][0] *= alpha0; oacc[dt][1] *= alpha0;
            oacc[dt][2] *= alpha1; oacc[dt][3] *= alpha1;
        }

        // ---- O += P @ V, P permuted C-frag -> A-frag via shfl
#pragma unroll
        for (int ks = 0; ks < 8; ks++) {
            float e0 = __shfl_sync(0xffffffffu, sacc[ks][0], srcA);
            float e1 = __shfl_sync(0xffffffffu, sacc[ks][1], srcA);
            float f0 = __shfl_sync(0xffffffffu, sacc[ks][0], srcB);
            float f1 = __shfl_sync(0xffffffffu, sacc[ks][1], srcB);
            float g0 = __shfl_sync(0xffffffffu, sacc[ks][2], srcA);
            float g1 = __shfl_sync(0xffffffffu, sacc[ks][3], srcA);
            float h0 = __shfl_sync(0xffffffffu, sacc[ks][2], srcB);
            float h1 = __shfl_sync(0xffffffffu, sacc[ks][3], srcB);
            uint32_t pa[4];
            pa[0] = f2tf32(odd ? e1 : e0);   // (gid,   tig)
            pa[1] = f2tf32(odd ? g1 : g0);   // (gid+8, tig)
            pa[2] = f2tf32(odd ? f1 : f0);   // (gid,   tig+4)
            pa[3] = f2tf32(odd ? h1 : h0);   // (gid+8, tig+4)
#pragma unroll
            for (int dt = 0; dt < 8; dt++) {
                const uint32_t* vp = &Vs[(ks * 8 + tig) * FS_V + dt * 8 + gid];
                MMA_TF32(oacc[dt], pa, vp[0], vp[4 * FS_V]);
            }
        }
        __syncthreads();   // all warps done with Ks/Vs

        // ---- prefetch next K/V tile
        if (n0 + 64 < PSEQ) {
#pragma unroll
            for (int u = 0; u < 8; u++) {
                int idx = u * 128 + tid;
                int r = idx >> 4, c4 = idx & 15;
                CP16(kb + (uint32_t)(r * FS_K + c4 * 4) * 4,
                     K + (rowbase + n0 + 64 + r) * HID + colbase + c4 * 4);
                CP16(vb + (uint32_t)(r * FS_V + c4 * 4) * 4,
                     V + (rowbase + n0 + 64 + r) * HID + colbase + c4 * 4);
            }
        }
        CP_COMMIT();
    }

    // ---- epilogue: write ctx pre-rounded to tf32 (feeds out-proj)
    float inv0 = 1.0f / l0;
    float inv1 = 1.0f / l1;
    size_t r0 = rowbase + q0 + wid * 16 + gid;
#pragma unroll
    for (int dt = 0; dt < 8; dt++) {
        int c = colbase + dt * 8 + tig * 2;
        uint32_t o00 = f2tf32(oacc[dt][0] * inv0);
        uint32_t o01 = f2tf32(oacc[dt][1] * inv0);
        uint32_t o10 = f2tf32(oacc[dt][2] * inv1);
        uint32_t o11 = f2tf32(oacc[dt][3] * inv1);
        *(float2*)(O + r0 * HID + c) =
            make_float2(__uint_as_float(o00), __uint_as_float(o01));
        *(float2*)(O + (r0 + 8) * HID + c) =
            make_float2(__uint_as_float(o10), __uint_as_float(o11));
    }
}

// ---------------------------------------------------------------------------
extern "C" void kernel_launch(void* const* d_in, const int* in_sizes, int n_in,
                              void* d_out, int out_size)
{
    const float* X  = (const float*)d_in[0];
    const float* Wq = (const float*)d_in[1];
    const float* bq = (const float*)d_in[2];
    const float* Wk = (const float*)d_in[3];
    const float* bk = (const float*)d_in[4];
    const float* Wv = (const float*)d_in[5];
    const float* bv = (const float*)d_in[6];
    const float* Wo = (const float*)d_in[7];
    const float* bo = (const float*)d_in[8];
    float* out = (float*)d_out;

    static float *pxtf = nullptr, *pwtf = nullptr,
                 *pq = nullptr, *pk = nullptr, *pv = nullptr, *pctx = nullptr;
    if (!pq) {
        cudaGetSymbolAddress((void**)&pxtf, g_xtf);
        cudaGetSymbolAddress((void**)&pwtf, g_wtf);
        cudaGetSymbolAddress((void**)&pq, g_q);
        cudaGetSymbolAddress((void**)&pk, g_k);
        cudaGetSymbolAddress((void**)&pv, g_v);
        cudaGetSymbolAddress((void**)&pctx, g_ctx);
        cudaFuncSetAttribute(gemm_mma, cudaFuncAttributeMaxDynamicSharedMemorySize, GEMM_SMEM);
    }

    // pre-round X and all weights to tf32
    const int n4x = NROWS * HID / 4;          // 3145728
    const int n4w = HID * HID / 4;            // 147456
    round_tf32_k<<<(n4x + 255) / 256, 256>>>(X, pxtf, n4x);
    round_w4_k<<<dim3((n4w + 255) / 256, 4), 256>>>(Wq, Wk, Wv, Wo, pwtf, n4w);

    dim3 gproj(HID / 128, NROWS / 128);   // (6, 128)
    gemm_mma<<<gproj, 128, GEMM_SMEM>>>(pxtf, pwtf + 0 * HID * HID, bq, pq, 1);
    gemm_mma<<<gproj, 128, GEMM_SMEM>>>(pxtf, pwtf + 1 * HID * HID, bk, pk, 1);
    gemm_mma<<<gproj, 128, GEMM_SMEM>>>(pxtf, pwtf + 2 * HID * HID, bv, pv, 1);

    dim3 gattn(PSEQ / 64, NH, NROWS / PSEQ);  // (8, 12, 32)
    flash_mma<<<gattn, 128>>>(pq, pk, pv, pctx);

    gemm_mma<<<gproj, 128, GEMM_SMEM>>>(pctx, pwtf + 3 * HID * HID, bo, out, 0);
}

// round 9
// speedup vs baseline: 1.4276x; 1.4276x over previous
#include <cuda_runtime.h>
#include <cstdint>

#define NROWS 16384   // B*M*P = 8*4*512
#define HID   768
#define NH    12
#define HS    64
#define PSEQ  512

// Scratch (allocation-free rule: __device__ globals)
__device__ float g_xtf[NROWS * HID];
__device__ float g_wtf[4 * HID * HID];
__device__ float g_q[NROWS * HID];
__device__ float g_k[NROWS * HID];
__device__ float g_v[NROWS * HID];
__device__ float g_ctx[NROWS * HID];

// ---------------------------------------------------------------------------
// helpers
// ---------------------------------------------------------------------------
__device__ __forceinline__ uint32_t f2tf32(float f) {
    uint32_t r;
    asm("cvt.rna.tf32.f32 %0, %1;" : "=r"(r) : "f"(f));
    return r;
}
__device__ __forceinline__ uint32_t smem_u32(const void* p) {
    uint32_t a;
    asm("{ .reg .u64 t; cvta.to.shared.u64 t, %1; cvt.u32.u64 %0, t; }" : "=r"(a) : "l"(p));
    return a;
}
#define CP16(dst_u32, src_ptr) \
    asm volatile("cp.async.cg.shared.global [%0], [%1], 16;" :: "r"(dst_u32), "l"(src_ptr) : "memory")
#define CP_COMMIT() asm volatile("cp.async.commit_group;" ::: "memory")
#define CP_WAIT(n)  asm volatile("cp.async.wait_group %0;" :: "n"(n) : "memory")

// D += A*B, m16n8k8 tf32 (row.col)
#define MMA_TF32(d, a, b0, b1) \
    asm volatile("mma.sync.aligned.m16n8k8.row.col.f32.tf32.tf32.f32 " \
        "{%0,%1,%2,%3}, {%4,%5,%6,%7}, {%8,%9}, {%0,%1,%2,%3};" \
        : "+f"((d)[0]), "+f"((d)[1]), "+f"((d)[2]), "+f"((d)[3]) \
        : "r"((a)[0]), "r"((a)[1]), "r"((a)[2]), "r"((a)[3]), "r"(b0), "r"(b1))

// ---------------------------------------------------------------------------
// Pre-round fp32 -> tf32-in-fp32.
// ---------------------------------------------------------------------------
__global__ __launch_bounds__(256) void round_tf32_k(
    const float* __restrict__ in, float* __restrict__ out, int n4)
{
    int i = blockIdx.x * 256 + threadIdx.x;
    if (i < n4) {
        float4 v = ((const float4*)in)[i];
        ((uint4*)out)[i] = make_uint4(f2tf32(v.x), f2tf32(v.y), f2tf32(v.z), f2tf32(v.w));
    }
}
// batched: 4 weight matrices in one launch (blockIdx.y selects source)
__global__ __launch_bounds__(256) void round_w4_k(
    const float* __restrict__ w0, const float* __restrict__ w1,
    const float* __restrict__ w2, const float* __restrict__ w3,
    float* __restrict__ out, int n4each)
{
    const float* src = (blockIdx.y == 0) ? w0 : (blockIdx.y == 1) ? w1
                     : (blockIdx.y == 2) ? w2 : w3;
    float* dst = out + (size_t)blockIdx.y * n4each * 4;
    int i = blockIdx.x * 256 + threadIdx.x;
    if (i < n4each) {
        float4 v = ((const float4*)src)[i];
        ((uint4*)dst)[i] = make_uint4(f2tf32(v.x), f2tf32(v.y), f2tf32(v.z), f2tf32(v.w));
    }
}

// ===========================================================================
// GEMM: C[16384,768] = A @ W + bias  (A, W pre-rounded to tf32)
// tile 128x128x32, 256 threads = 8 warps (2x4), warp tile 64x32.  [R5 config]
// 2-stage cp.async pipeline; BS_STRIDE=136 (=8 mod 32) -> conflict-free B frags.
// ===========================================================================
#define AS_STRIDE 36    // dwords; =4 mod 32 -> A-frag lanes gid*4+tig distinct
#define BS_STRIDE 136   // dwords; =8 mod 32 -> B-frag lanes tig*8+gid distinct
#define A_BUF (128 * AS_STRIDE)
#define B_BUF (32 * BS_STRIDE)
#define KITERS (HID / 32)   // 24
#define GEMM_SMEM ((2 * A_BUF + 2 * B_BUF) * 4)   // 71680 bytes

__global__ __launch_bounds__(256) void gemm_mma(
    const float* __restrict__ A, const float* __restrict__ W,
    const float* __restrict__ bias, float* __restrict__ C, int round_out)
{
    extern __shared__ __align__(16) uint32_t sm[];
    uint32_t* AsBase = sm;                 // [2][A_BUF]
    uint32_t* BsBase = sm + 2 * A_BUF;     // [2][B_BUF]
    const uint32_t as_addr = smem_u32(AsBase);
    const uint32_t bs_addr = smem_u32(BsBase);

    const int tid = threadIdx.x;
    const int wid = tid >> 5;
    const int lane = tid & 31;
    const int gid = lane >> 2;
    const int tig = lane & 3;
    const int wm = wid >> 2;       // 0..1 -> 64 rows
    const int wn = wid & 3;        // 0..3 -> 32 cols
    const int bm = blockIdx.y * 128;
    const int bn = blockIdx.x * 128;

    float acc[4][4][4] = {};

    // issue cp.asyncs for K-tile `it` into buffer it&1
    auto issue_tile = [&](int it) {
        const int k0 = it * 32;
        const uint32_t ad = as_addr + (uint32_t)((it & 1) * A_BUF * 4);
        const uint32_t bd = bs_addr + (uint32_t)((it & 1) * B_BUF * 4);
#pragma unroll
        for (int u = 0; u < 4; u++) {
            int idx = u * 256 + tid;
            int r = idx >> 3, c4 = idx & 7;
            CP16(ad + (uint32_t)(r * AS_STRIDE + c4 * 4) * 4,
                 A + (size_t)(bm + r) * HID + k0 + c4 * 4);
        }
#pragma unroll
        for (int u = 0; u < 4; u++) {
            int idx = u * 256 + tid;
            int kr = idx >> 5, nc = idx & 31;
            CP16(bd + (uint32_t)(kr * BS_STRIDE + nc * 4) * 4,
                 W + (size_t)(k0 + kr) * HID + bn + nc * 4);
        }
    };

    issue_tile(0);
    CP_COMMIT();

#pragma unroll 1
    for (int it = 0; it < KITERS; it++) {
        if (it + 1 < KITERS) {
            issue_tile(it + 1);
            CP_COMMIT();
            CP_WAIT(1);
        } else {
            CP_WAIT(0);
        }
        __syncthreads();

        const uint32_t* As = AsBase + (it & 1) * A_BUF;
        const uint32_t* Bs = BsBase + (it & 1) * B_BUF;
#pragma unroll
        for (int ks = 0; ks < 4; ks++) {
            uint32_t a[4][4];
#pragma unroll
            for (int mt = 0; mt < 4; mt++) {
                const uint32_t* p = &As[(wm * 64 + mt * 16 + gid) * AS_STRIDE + ks * 8 + tig];
                a[mt][0] = p[0];
                a[mt][1] = p[8 * AS_STRIDE];
                a[mt][2] = p[4];
                a[mt][3] = p[8 * AS_STRIDE + 4];
            }
#pragma unroll
            for (int nt = 0; nt < 4; nt++) {
                const uint32_t* p = &Bs[(ks * 8 + tig) * BS_STRIDE + wn * 32 + nt * 8 + gid];
                uint32_t b0 = p[0];
                uint32_t b1 = p[4 * BS_STRIDE];
#pragma unroll
                for (int mt = 0; mt < 4; mt++)
                    MMA_TF32(acc[mt][nt], a[mt], b0, b1);
            }
        }
        __syncthreads();
    }

    // epilogue
#pragma unroll
    for (int mt = 0; mt < 4; mt++) {
        int r0 = bm + wm * 64 + mt * 16 + gid;
#pragma unroll
        for (int nt = 0; nt < 4; nt++) {
            int c = bn + wn * 32 + nt * 8 + tig * 2;
            float b0 = bias[c], b1 = bias[c + 1];
            float o00 = acc[mt][nt][0] + b0, o01 = acc[mt][nt][1] + b1;
            float o10 = acc[mt][nt][2] + b0, o11 = acc[mt][nt][3] + b1;
            if (round_out) {
                o00 = __uint_as_float(f2tf32(o00));
                o01 = __uint_as_float(f2tf32(o01));
                o10 = __uint_as_float(f2tf32(o10));
                o11 = __uint_as_float(f2tf32(o11));
            }
            *(float2*)(C + (size_t)r0 * HID + c) = make_float2(o00, o01);
            *(float2*)(C + (size_t)(r0 + 8) * HID + c) = make_float2(o10, o11);
        }
    }
}

// ===========================================================================
// Flash attention with mma.sync tf32 (Q,K,V pre-rounded to tf32).  [R5 config]
// Block = 128 thr (4 warps), q-tile 64 (warp owns 16 q-rows), KV tiles of 64.
// cp.async loads; softmax in registers; P round-trips through smem (aliases K).
// K/Q/P buffer stride 68 (=4 mod 32); V buffer stride 72 (=8 mod 32):
// all fragment read patterns bank-conflict-free.
// ===========================================================================
#define FS_K 68
#define FS_V 72

__global__ __launch_bounds__(128) void flash_mma(
    const float* __restrict__ Q, const float* __restrict__ K,
    const float* __restrict__ V, float* __restrict__ O)
{
    __shared__ __align__(16) uint32_t KPs[64 * FS_K];
    __shared__ __align__(16) uint32_t Vs[64 * FS_V];
    const uint32_t kb = smem_u32(KPs);
    const uint32_t vb = smem_u32(Vs);

    const int tid = threadIdx.x;
    const int wid = tid >> 5;
    const int lane = tid & 31;
    const int gid = lane >> 2;
    const int tig = lane & 3;
    const int q0 = blockIdx.x * 64;
    const int head = blockIdx.y;
    const int bmi = blockIdx.z;
    const size_t rowbase = (size_t)bmi * PSEQ;
    const int colbase = head * HS;

    // ---- load Q tile (64x64) via cp.async, lift to register fragments
#pragma unroll
    for (int u = 0; u < 8; u++) {
        int idx = u * 128 + tid;
        int r = idx >> 4, c4 = idx & 15;
        CP16(kb + (uint32_t)(r * FS_K + c4 * 4) * 4,
             Q + (rowbase + q0 + r) * HID + colbase + c4 * 4);
    }
    CP_COMMIT();
    CP_WAIT(0);
    __syncthreads();
    uint32_t qf[8][4];
#pragma unroll
    for (int ks = 0; ks < 8; ks++) {
        const uint32_t* p = &KPs[(wid * 16 + gid) * FS_K + ks * 8 + tig];
        qf[ks][0] = p[0];
        qf[ks][1] = p[8 * FS_K];
        qf[ks][2] = p[4];
        qf[ks][3] = p[8 * FS_K + 4];
    }
    __syncthreads();

    float m0 = -1e30f, m1 = -1e30f, l0 = 0.f, l1 = 0.f;
    float oacc[8][4] = {};

#pragma unroll 1
    for (int n0 = 0; n0 < PSEQ; n0 += 64) {
        // ---- load K and V tiles (64x64 each) via cp.async
#pragma unroll
        for (int u = 0; u < 8; u++) {
            int idx = u * 128 + tid;
            int r = idx >> 4, c4 = idx & 15;
            const float* ksrc = K + (rowbase + n0 + r) * HID + colbase + c4 * 4;
            const float* vsrc = V + (rowbase + n0 + r) * HID + colbase + c4 * 4;
            CP16(kb + (uint32_t)(r * FS_K + c4 * 4) * 4, ksrc);
            CP16(vb + (uint32_t)(r * FS_V + c4 * 4) * 4, vsrc);
        }
        CP_COMMIT();
        CP_WAIT(0);
        __syncthreads();

        // ---- S = Q K^T (warp's 16 q-rows x 64 kv)
        float sacc[8][4] = {};
#pragma unroll
        for (int ks = 0; ks < 8; ks++) {
#pragma unroll
            for (int nt = 0; nt < 8; nt++) {
                const uint32_t* p = &KPs[(nt * 8 + gid) * FS_K + ks * 8 + tig];
                MMA_TF32(sacc[nt], qf[ks], p[0], p[4]);
            }
        }

        // ---- online softmax (rows gid, gid+8 of warp's 16)
        float rmax0 = -1e30f, rmax1 = -1e30f;
#pragma unroll
        for (int nt = 0; nt < 8; nt++) {
            sacc[nt][0] *= 0.125f; sacc[nt][1] *= 0.125f;
            sacc[nt][2] *= 0.125f; sacc[nt][3] *= 0.125f;
            rmax0 = fmaxf(rmax0, fmaxf(sacc[nt][0], sacc[nt][1]));
            rmax1 = fmaxf(rmax1, fmaxf(sacc[nt][2], sacc[nt][3]));
        }
        rmax0 = fmaxf(rmax0, __shfl_xor_sync(0xffffffffu, rmax0, 1));
        rmax0 = fmaxf(rmax0, __shfl_xor_sync(0xffffffffu, rmax0, 2));
        rmax1 = fmaxf(rmax1, __shfl_xor_sync(0xffffffffu, rmax1, 1));
        rmax1 = fmaxf(rmax1, __shfl_xor_sync(0xffffffffu, rmax1, 2));
        float m0n = fmaxf(m0, rmax0);
        float m1n = fmaxf(m1, rmax1);
        float alpha0 = __expf(m0 - m0n);
        float alpha1 = __expf(m1 - m1n);
        float rs0 = 0.f, rs1 = 0.f;
#pragma unroll
        for (int nt = 0; nt < 8; nt++) {
            sacc[nt][0] = __expf(sacc[nt][0] - m0n);
            sacc[nt][1] = __expf(sacc[nt][1] - m0n);
            sacc[nt][2] = __expf(sacc[nt][2] - m1n);
            sacc[nt][3] = __expf(sacc[nt][3] - m1n);
            rs0 += sacc[nt][0] + sacc[nt][1];
            rs1 += sacc[nt][2] + sacc[nt][3];
        }
        rs0 += __shfl_xor_sync(0xffffffffu, rs0, 1);
        rs0 += __shfl_xor_sync(0xffffffffu, rs0, 2);
        rs1 += __shfl_xor_sync(0xffffffffu, rs1, 1);
        rs1 += __shfl_xor_sync(0xffffffffu, rs1, 2);
        l0 = l0 * alpha0 + rs0;
        l1 = l1 * alpha1 + rs1;
        m0 = m0n; m1 = m1n;
#pragma unroll
        for (int dt = 0; dt < 8; dt++) {
            oacc[dt][0] *= alpha0; oacc[dt][1] *= alpha0;
            oacc[dt][2] *= alpha1; oacc[dt][3] *= alpha1;
        }
        __syncthreads();   // everyone done reading KPs as K

        // ---- write P (64x64) into KPs
#pragma unroll
        for (int nt = 0; nt < 8; nt++) {
            uint32_t* p = &KPs[(wid * 16 + gid) * FS_K + nt * 8 + tig * 2];
            p[0] = f2tf32(sacc[nt][0]);
            p[1] = f2tf32(sacc[nt][1]);
            p[8 * FS_K + 0] = f2tf32(sacc[nt][2]);
            p[8 * FS_K + 1] = f2tf32(sacc[nt][3]);
        }
        __syncthreads();

        // ---- O += P @ V
#pragma unroll
        for (int ks = 0; ks < 8; ks++) {
            uint32_t pa[4];
            const uint32_t* pp = &KPs[(wid * 16 + gid) * FS_K + ks * 8 + tig];
            pa[0] = pp[0];
            pa[1] = pp[8 * FS_K];
            pa[2] = pp[4];
            pa[3] = pp[8 * FS_K + 4];
#pragma unroll
            for (int dt = 0; dt < 8; dt++) {
                const uint32_t* vp = &Vs[(ks * 8 + tig) * FS_V + dt * 8 + gid];
                MMA_TF32(oacc[dt], pa, vp[0], vp[4 * FS_V]);
            }
        }
        __syncthreads();   // before next tile overwrites KPs/Vs
    }

    // ---- epilogue: write ctx pre-rounded to tf32 (feeds out-proj)
    float inv0 = 1.0f / l0;
    float inv1 = 1.0f / l1;
    size_t r0 = rowbase + q0 + wid * 16 + gid;
#pragma unroll
    for (int dt = 0; dt < 8; dt++) {
        int c = colbase + dt * 8 + tig * 2;
        uint32_t o00 = f2tf32(oacc[dt][0] * inv0);
        uint32_t o01 = f2tf32(oacc[dt][1] * inv0);
        uint32_t o10 = f2tf32(oacc[dt][2] * inv1);
        uint32_t o11 = f2tf32(oacc[dt][3] * inv1);
        *(float2*)(O + r0 * HID + c) =
            make_float2(__uint_as_float(o00), __uint_as_float(o01));
        *(float2*)(O + (r0 + 8) * HID + c) =
            make_float2(__uint_as_float(o10), __uint_as_float(o11));
    }
}

// ---------------------------------------------------------------------------
extern "C" void kernel_launch(void* const* d_in, const int* in_sizes, int n_in,
                              void* d_out, int out_size)
{
    const float* X  = (const float*)d_in[0];
    const float* Wq = (const float*)d_in[1];
    const float* bq = (const float*)d_in[2];
    const float* Wk = (const float*)d_in[3];
    const float* bk = (const float*)d_in[4];
    const float* Wv = (const float*)d_in[5];
    const float* bv = (const float*)d_in[6];
    const float* Wo = (const float*)d_in[7];
    const float* bo = (const float*)d_in[8];
    float* out = (float*)d_out;

    static float *pxtf = nullptr, *pwtf = nullptr,
                 *pq = nullptr, *pk = nullptr, *pv = nullptr, *pctx = nullptr;
    if (!pq) {
        cudaGetSymbolAddress((void**)&pxtf, g_xtf);
        cudaGetSymbolAddress((void**)&pwtf, g_wtf);
        cudaGetSymbolAddress((void**)&pq, g_q);
        cudaGetSymbolAddress((void**)&pk, g_k);
        cudaGetSymbolAddress((void**)&pv, g_v);
        cudaGetSymbolAddress((void**)&pctx, g_ctx);
        cudaFuncSetAttribute(gemm_mma, cudaFuncAttributeMaxDynamicSharedMemorySize, GEMM_SMEM);
    }

    // pre-round X and all weights to tf32
    const int n4x = NROWS * HID / 4;          // 3145728
    const int n4w = HID * HID / 4;            // 147456
    round_tf32_k<<<(n4x + 255) / 256, 256>>>(X, pxtf, n4x);
    round_w4_k<<<dim3((n4w + 255) / 256, 4), 256>>>(Wq, Wk, Wv, Wo, pwtf, n4w);

    dim3 gproj(HID / 128, NROWS / 128);   // (6, 128)
    gemm_mma<<<gproj, 256, GEMM_SMEM>>>(pxtf, pwtf + 0 * HID * HID, bq, pq, 1);
    gemm_mma<<<gproj, 256, GEMM_SMEM>>>(pxtf, pwtf + 1 * HID * HID, bk, pk, 1);
    gemm_mma<<<gproj, 256, GEMM_SMEM>>>(pxtf, pwtf + 2 * HID * HID, bv, pv, 1);

    dim3 gattn(PSEQ / 64, NH, NROWS / PSEQ);  // (8, 12, 32)
    flash_mma<<<gattn, 128>>>(pq, pk, pv, pctx);

    gemm_mma<<<gproj, 256, GEMM_SMEM>>>(pctx, pwtf + 3 * HID * HID, bo, out, 0);
}